// round 14
// baseline (speedup 1.0000x reference)
#include <cuda_runtime.h>
#include <cuda_fp16.h>
#include <math.h>

#define NATOMS  50000
#define NEDGE   1600000
#define NGRAPH  250
#define HDIM    64
#define NGAUSS  50
#define NB      3
#define MTAB    8192
#define KBITS   13
#define TABMAX  8.6700f
#define TABSCALE ((float)(MTAB - 1) / TABMAX)
#define TABSTEP  (TABMAX / (float)(MTAB - 1))
#define NSCANB  49

#define RPB        128
#define GEMM_GRID  ((NATOMS + RPB - 1) / RPB)
#define AS_STRIDE  72          // halves; 144B row pitch -> conflict-free LDSM

// ---------------- scratch ----------------------------------------------------
// g_base = [g_cnt: NATOMS ints][scan flags: 64 ints][g_gr: NGRAPH*HDIM floats]
// zeroed by ONE cudaMemsetAsync per call.
#define ZBASE_INTS (NATOMS + 64 + NGRAPH * HDIM)
__device__ int       g_base[ZBASE_INTS];
__device__ int       g_bval[64];                // gated by flags; no zeroing needed
__device__ __half    g_tabh[NB * MTAB * HDIM];
__device__ float     g_h[NATOMS * HDIM];
__device__ __half    g_hxh[NATOMS * HDIM];
__device__ __half    g_aggh[NATOMS * HDIM];
__device__ int       g_rp[NATOMS + 1];
__device__ int       g_rank[NEDGE];
__device__ unsigned  g_tmp[NEDGE];              // packed (src,knot) in edge order
__device__ unsigned  g_src[NEDGE];              // packed, dst-sorted

__device__ __forceinline__ int*   cnt_p()  { return g_base; }
__device__ __forceinline__ int*   flag_p() { return g_base + NATOMS; }
__device__ __forceinline__ float* gr_p()   { return (float*)(g_base + NATOMS + 64); }

__device__ __forceinline__ float ssp(float v) {
    return fmaxf(v, 0.0f) + log1pf(expf(-fabsf(v))) - 0.6931471805599453f;
}

__device__ __forceinline__ unsigned h2u(__half2 h) {
    unsigned u;
    asm("mov.b32 %0,%1;" : "=r"(u) : "r"(*(unsigned*)&h));
    return u;
}

// ---------------- mma.sync helpers ---------------------------------------------
__device__ __forceinline__ void ldmatrix_x4(unsigned& r0, unsigned& r1,
                                            unsigned& r2, unsigned& r3, unsigned addr) {
    asm volatile("ldmatrix.sync.aligned.m8n8.x4.shared.b16 {%0,%1,%2,%3},[%4];"
                 : "=r"(r0), "=r"(r1), "=r"(r2), "=r"(r3) : "r"(addr));
}
__device__ __forceinline__ void ldmatrix_x2_trans(unsigned& r0, unsigned& r1, unsigned addr) {
    asm volatile("ldmatrix.sync.aligned.m8n8.x2.trans.shared.b16 {%0,%1},[%2];"
                 : "=r"(r0), "=r"(r1) : "r"(addr));
}
__device__ __forceinline__ void mma16816(float& d0, float& d1, float& d2, float& d3,
                                         unsigned a0, unsigned a1, unsigned a2, unsigned a3,
                                         unsigned b0, unsigned b1) {
    asm volatile("mma.sync.aligned.m16n8k16.row.col.f32.f16.f16.f32 "
                 "{%0,%1,%2,%3},{%4,%5,%6,%7},{%8,%9},{%0,%1,%2,%3};"
                 : "+f"(d0), "+f"(d1), "+f"(d2), "+f"(d3)
                 : "r"(a0), "r"(a1), "r"(a2), "r"(a3), "r"(b0), "r"(b1));
}

__device__ __forceinline__ void mma_gemm(const __half* As, const __half* Bs,
                                         int w, int lane, float (&d)[8][4]) {
    unsigned as_base = (unsigned)__cvta_generic_to_shared(As);
    unsigned bs_base = (unsigned)__cvta_generic_to_shared(Bs);
    unsigned a[4][4];
    int arow = 16 * w + (lane & 15);
    int acol = (lane >> 4) * 8;
    #pragma unroll
    for (int ks = 0; ks < 4; ks++) {
        unsigned addr = as_base + ((arow * AS_STRIDE + ks * 16 + acol) << 1);
        ldmatrix_x4(a[ks][0], a[ks][1], a[ks][2], a[ks][3], addr);
    }
    int brow = lane & 15;
    #pragma unroll
    for (int j = 0; j < 8; j++) {
        #pragma unroll
        for (int ks = 0; ks < 4; ks++) {
            unsigned b0, b1;
            unsigned addr = bs_base + (((ks * 16 + brow) * AS_STRIDE + j * 8) << 1);
            ldmatrix_x2_trans(b0, b1, addr);
            mma16816(d[j][0], d[j][1], d[j][2], d[j][3],
                     a[ks][0], a[ks][1], a[ks][2], a[ks][3], b0, b1);
        }
    }
}

__device__ __forceinline__ void zero_d(float (&d)[8][4]) {
    #pragma unroll
    for (int j = 0; j < 8; j++)
        #pragma unroll
        for (int p = 0; p < 4; p++) d[j][p] = 0.0f;
}

__device__ __forceinline__ void stage_a_h16(__half* As, const __half* __restrict__ src,
                                            int r0, int tid) {
    #pragma unroll
    for (int it = 0; it < 4; it++) {
        int idx = (it * 256 + tid) * 8;
        int row = idx >> 6, c = idx & 63;
        int gr = min(r0 + row, NATOMS - 1);
        uint4 v = __ldg((const uint4*)(src + (size_t)gr * 64 + c));
        *(uint4*)(As + row * AS_STRIDE + c) = v;
    }
}

__device__ __forceinline__ void stage_w16(__half* Bs, const float* __restrict__ W, int tid) {
    #pragma unroll
    for (int it = 0; it < 4; it++) {
        int idx = (it * 256 + tid) * 4;
        int row = idx >> 6, c = idx & 63;
        float4 v = __ldg((const float4*)(W + idx));
        uint2 u;
        u.x = h2u(__floats2half2_rn(v.x, v.y));
        u.y = h2u(__floats2half2_rn(v.z, v.w));
        *(uint2*)(Bs + row * AS_STRIDE + c) = u;
    }
}

// ---------------- CSR build ----------------------------------------------------
// hist + distance + rank + packed-rec (edge order)
__global__ void k_hist(const float* __restrict__ pos, const int* __restrict__ ei) {
    int e4 = (blockIdx.x * blockDim.x + threadIdx.x) * 4;
    if (e4 >= NEDGE) return;
    int4 s = __ldg((const int4*)(ei + e4));
    int4 t = __ldg((const int4*)(ei + NEDGE + e4));
    int ss[4] = {s.x, s.y, s.z, s.w};
    int tt[4] = {t.x, t.y, t.z, t.w};
    int4 rk;
    unsigned rec[4];
    #pragma unroll
    for (int i = 0; i < 4; i++) {
        float dx = __ldg(pos + 3 * tt[i] + 0) - __ldg(pos + 3 * ss[i] + 0);
        float dy = __ldg(pos + 3 * tt[i] + 1) - __ldg(pos + 3 * ss[i] + 1);
        float dz = __ldg(pos + 3 * tt[i] + 2) - __ldg(pos + 3 * ss[i] + 2);
        float d = sqrtf(dx * dx + dy * dy + dz * dz);
        int knot = min((int)(d * TABSCALE + 0.5f), MTAB - 1);
        rec[i] = ((unsigned)ss[i] << KBITS) | (unsigned)knot;
    }
    int* cnt = cnt_p();
    rk.x = atomicAdd(&cnt[tt[0]], 1);
    rk.y = atomicAdd(&cnt[tt[1]], 1);
    rk.z = atomicAdd(&cnt[tt[2]], 1);
    rk.w = atomicAdd(&cnt[tt[3]], 1);
    *(int4*)(g_rank + e4) = rk;
    *(uint4*)(g_tmp + e4) = make_uint4(rec[0], rec[1], rec[2], rec[3]);
}

// single-pass decoupled-lookback exclusive scan of g_cnt -> g_rp
__global__ __launch_bounds__(1024) void k_scan() {
    __shared__ int wsum[32];
    __shared__ int s_btot;
    __shared__ int s_prev;
    int tid = threadIdx.x, lane = tid & 31, wid = tid >> 5, b = blockIdx.x;
    int i = b * 1024 + tid;
    int v = (i < NATOMS) ? cnt_p()[i] : 0;
    int incl = v;
    #pragma unroll
    for (int off = 1; off < 32; off <<= 1) {
        int n = __shfl_up_sync(0xffffffffu, incl, off);
        if (lane >= off) incl += n;
    }
    if (lane == 31) wsum[wid] = incl;
    __syncthreads();
    if (wid == 0) {
        int wv = wsum[lane];
        int wincl = wv;
        #pragma unroll
        for (int off = 1; off < 32; off <<= 1) {
            int n = __shfl_up_sync(0xffffffffu, wincl, off);
            if (lane >= off) wincl += n;
        }
        wsum[lane] = wincl - wv;           // exclusive warp prefix
        if (lane == 31) s_btot = wincl;    // block total
    }
    __syncthreads();

    if (tid == 0) {
        int prev = 0;
        if (b > 0) {
            while (atomicAdd(&flag_p()[b - 1], 0) == 0) { }
            prev = atomicAdd(&g_bval[b - 1], 0);
        }
        g_bval[b] = prev + s_btot;
        __threadfence();
        atomicExch(&flag_p()[b], 1);
        s_prev = prev;
    }
    __syncthreads();

    int excl = wsum[wid] + incl - v + s_prev;
    if (i < NATOMS) g_rp[i] = excl;
    if (b == NSCANB - 1 && tid == 1023) g_rp[NATOMS] = NEDGE;
}

// lightweight permutation scatter: slot = rp[dst] + rank
__global__ void k_scatter(const int* __restrict__ ei) {
    int e4 = (blockIdx.x * blockDim.x + threadIdx.x) * 4;
    if (e4 >= NEDGE) return;
    int4 t = __ldg((const int4*)(ei + NEDGE + e4));
    int4 rk = *(const int4*)(g_rank + e4);
    uint4 rec = *(const uint4*)(g_tmp + e4);
    g_src[__ldg(&g_rp[t.x]) + rk.x] = rec.x;
    g_src[__ldg(&g_rp[t.y]) + rk.y] = rec.y;
    g_src[__ldg(&g_rp[t.z]) + rk.z] = rec.z;
    g_src[__ldg(&g_rp[t.w]) + rk.w] = rec.w;
}

// ---------------- build Wf(d) table (fp16) -------------------------------------
__global__ __launch_bounds__(64) void k_table(
    const float* __restrict__ w1, const float* __restrict__ b1,
    const float* __restrict__ w2, const float* __restrict__ b2)
{
    __shared__ float w1s[NGAUSS * 64];
    __shared__ float w2s[64 * 64];
    __shared__ float b1s[64], b2s[64];
    __shared__ float rbfs[NGAUSS];
    __shared__ float t1s[64];

    const int KPB = 32;
    int t  = blockIdx.x / (MTAB / KPB);
    int kb = blockIdx.x % (MTAB / KPB);
    int tid = threadIdx.x;

    for (int i = tid; i < NGAUSS * 64; i += 64) w1s[i] = w1[t * NGAUSS * 64 + i];
    for (int i = tid; i < 64 * 64;     i += 64) w2s[i] = w2[t * 64 * 64 + i];
    b1s[tid] = b1[t * 64 + tid];
    b2s[tid] = b2[t * 64 + tid];

    const float step  = 10.0f / 49.0f;
    const float coeff = -0.5f / (step * step);

    for (int kk = 0; kk < KPB; kk++) {
        int knot = kb * KPB + kk;
        float dv = (float)knot * TABSTEP;
        __syncthreads();
        if (tid < NGAUSS) {
            float dd = dv - (float)tid * step;
            rbfs[tid] = expf(coeff * dd * dd);
        }
        __syncthreads();
        float a = b1s[tid];
        #pragma unroll 10
        for (int j = 0; j < NGAUSS; j++) a += rbfs[j] * w1s[j * 64 + tid];
        t1s[tid] = ssp(a);
        __syncthreads();
        float a2 = b2s[tid];
        #pragma unroll 16
        for (int k = 0; k < 64; k++) a2 += t1s[k] * w2s[k * 64 + tid];
        float C = 0.5f * (cosf(dv * 0.31415926535897931f) + 1.0f);
        g_tabh[((size_t)t * MTAB + knot) * 64 + tid] = __float2half_rn(a2 * C);
    }
}

// ---------------- fused embed + cf1(t=0), tensor-core GEMM ----------------------
__global__ __launch_bounds__(256) void k_embed_cf1(
    const int* __restrict__ z, const float* __restrict__ emb,
    const float* __restrict__ W)
{
    __shared__ __half As[128 * AS_STRIDE];
    __shared__ __half Bs[64 * AS_STRIDE];
    int tid = threadIdx.x, lane = tid & 31, w = tid >> 5;
    int r0 = blockIdx.x * RPB;

    #pragma unroll
    for (int it = 0; it < 8; it++) {
        int idx = (it * 256 + tid) * 4;
        int row = idx >> 6, c = idx & 63;
        int gr = min(r0 + row, NATOMS - 1);
        int zi = __ldg(z + gr);
        float4 v = __ldg((const float4*)(emb + (size_t)zi * 64 + c));
        if (r0 + row < NATOMS)
            *(float4*)(g_h + (size_t)(r0 + row) * 64 + c) = v;
        uint2 u;
        u.x = h2u(__floats2half2_rn(v.x, v.y));
        u.y = h2u(__floats2half2_rn(v.z, v.w));
        *(uint2*)(As + row * AS_STRIDE + c) = u;
    }
    stage_w16(Bs, W, tid);
    __syncthreads();

    float d[8][4];
    zero_d(d);
    mma_gemm(As, Bs, w, lane, d);

    int g = lane >> 2, t = lane & 3;
    int ra = r0 + 16 * w + g;
    #pragma unroll
    for (int j = 0; j < 8; j++) {
        int col = 8 * j + 2 * t;
        if (ra < NATOMS)
            *(__half2*)(g_hxh + (size_t)ra * 64 + col) = __floats2half2_rn(d[j][0], d[j][1]);
        if (ra + 8 < NATOMS)
            *(__half2*)(g_hxh + (size_t)(ra + 8) * 64 + col) = __floats2half2_rn(d[j][2], d[j][3]);
    }
}

// ---------------- gather-aggregate (fp16 output; one warp per node) --------------
__device__ __forceinline__ void agg_acc(uint4 tv, uint4 hv, float* a) {
    __half2 p0 = __hmul2(*(__half2*)&tv.x, *(__half2*)&hv.x);
    __half2 p1 = __hmul2(*(__half2*)&tv.y, *(__half2*)&hv.y);
    __half2 p2 = __hmul2(*(__half2*)&tv.z, *(__half2*)&hv.z);
    __half2 p3 = __hmul2(*(__half2*)&tv.w, *(__half2*)&hv.w);
    float2 f0 = __half22float2(p0);
    float2 f1 = __half22float2(p1);
    float2 f2 = __half22float2(p2);
    float2 f3 = __half22float2(p3);
    a[0] += f0.x; a[1] += f0.y;
    a[2] += f1.x; a[3] += f1.y;
    a[4] += f2.x; a[5] += f2.y;
    a[6] += f3.x; a[7] += f3.y;
}

__global__ __launch_bounds__(256) void k_agg(int t) {
    int node = blockIdx.x * 8 + (threadIdx.x >> 5);
    if (node >= NATOMS) return;
    int lane = threadIdx.x & 31;
    int grp  = lane >> 3;
    int fl   = lane & 7;
    int beg = __ldg(&g_rp[node]), end = __ldg(&g_rp[node + 1]);

    float a[8];
    #pragma unroll
    for (int i = 0; i < 8; i++) a[i] = 0.0f;
    const __half* tb = g_tabh + (size_t)t * MTAB * 64;

    int base = beg;
    for (; base + 32 <= end; base += 32) {
        unsigned rec = __ldg(&g_src[base + lane]);
        #pragma unroll
        for (int j = 0; j < 32; j += 8) {
            unsigned rA = __shfl_sync(0xffffffffu, rec, j + grp);
            unsigned rB = __shfl_sync(0xffffffffu, rec, j + 4 + grp);
            uint4 tA = __ldg((const uint4*)(tb + (size_t)(rA & (MTAB - 1)) * 64) + fl);
            uint4 tB = __ldg((const uint4*)(tb + (size_t)(rB & (MTAB - 1)) * 64) + fl);
            uint4 hA = __ldg((const uint4*)(g_hxh + (size_t)(rA >> KBITS) * 64) + fl);
            uint4 hB = __ldg((const uint4*)(g_hxh + (size_t)(rB >> KBITS) * 64) + fl);
            agg_acc(tA, hA, a);
            agg_acc(tB, hB, a);
        }
    }
    if (base < end) {
        unsigned rec = 0u;
        if (base + lane < end) rec = __ldg(&g_src[base + lane]);
        int n = end - base;
        for (int j = 0; j < n; j += 4) {
            unsigned r = __shfl_sync(0xffffffffu, rec, j + grp);
            if (j + grp < n) {
                uint4 tv = __ldg((const uint4*)(tb + (size_t)(r & (MTAB - 1)) * 64) + fl);
                uint4 hv = __ldg((const uint4*)(g_hxh + (size_t)(r >> KBITS) * 64) + fl);
                agg_acc(tv, hv, a);
            }
        }
    }

    #pragma unroll
    for (int i = 0; i < 8; i++) {
        a[i] += __shfl_down_sync(0xffffffffu, a[i], 16);
        a[i] += __shfl_down_sync(0xffffffffu, a[i], 8);
    }
    if (grp == 0) {
        uint4 o;
        o.x = h2u(__floats2half2_rn(a[0], a[1]));
        o.y = h2u(__floats2half2_rn(a[2], a[3]));
        o.z = h2u(__floats2half2_rn(a[4], a[5]));
        o.w = h2u(__floats2half2_rn(a[6], a[7]));
        *(uint4*)(g_aggh + (size_t)node * 64 + fl * 8) = o;
    }
}

// ---------------- cf2lin: 3 tensor-core GEMMs; last interaction fuses readout ----
template <bool FUSE_NEXT>
__global__ __launch_bounds__(256) void k_cf2lin(
    const float* __restrict__ W1, const float* __restrict__ B1,
    const float* __restrict__ W2, const float* __restrict__ B2,
    const float* __restrict__ W3, const int* __restrict__ batch)
{
    __shared__ __half As[128 * AS_STRIDE];
    __shared__ __half Bs[64 * AS_STRIDE];
    __shared__ float sbias[64];
    int tid = threadIdx.x, lane = tid & 31, w = tid >> 5;
    int r0 = blockIdx.x * RPB;
    int g = lane >> 2, tq = lane & 3;
    int lra = 16 * w + g;

    // ---- GEMM1: us = ssp(agg @ W1 + B1) ----
    stage_a_h16(As, g_aggh, r0, tid);
    stage_w16(Bs, W1, tid);
    if (tid < 64) sbias[tid] = __ldg(B1 + tid);
    __syncthreads();

    float d[8][4];
    zero_d(d);
    mma_gemm(As, Bs, w, lane, d);

    #pragma unroll
    for (int j = 0; j < 8; j++) {
        int col = 8 * j + 2 * tq;
        float b0v = sbias[col], b1v = sbias[col + 1];
        *(__half2*)(As + lra * AS_STRIDE + col) =
            __floats2half2_rn(ssp(d[j][0] + b0v), ssp(d[j][1] + b1v));
        *(__half2*)(As + (lra + 8) * AS_STRIDE + col) =
            __floats2half2_rn(ssp(d[j][2] + b0v), ssp(d[j][3] + b1v));
    }
    __syncthreads();
    stage_w16(Bs, W2, tid);
    if (tid < 64) sbias[tid] = __ldg(B2 + tid);
    __syncthreads();

    // ---- GEMM2: x = us @ W2 + B2 ; hn = h + x ----
    zero_d(d);
    mma_gemm(As, Bs, w, lane, d);

    int ra = r0 + lra;
    int gra = min(ra, NATOMS - 1), grb = min(ra + 8, NATOMS - 1);
    int ba = 0, bb = 0;
    if (!FUSE_NEXT) {
        ba = __ldg(batch + gra);
        bb = __ldg(batch + grb);
    }
    float* grf = gr_p();
    #pragma unroll
    for (int j = 0; j < 8; j++) {
        int col = 8 * j + 2 * tq;
        float b0v = sbias[col], b1v = sbias[col + 1];
        float2 h0 = *(const float2*)(g_h + (size_t)gra * 64 + col);
        float2 h1 = *(const float2*)(g_h + (size_t)grb * 64 + col);
        float n0 = h0.x + d[j][0] + b0v, n1 = h0.y + d[j][1] + b1v;
        float n2 = h1.x + d[j][2] + b0v, n3 = h1.y + d[j][3] + b1v;
        if (FUSE_NEXT) {
            if (ra < NATOMS)
                *(float2*)(g_h + (size_t)ra * 64 + col) = make_float2(n0, n1);
            if (ra + 8 < NATOMS)
                *(float2*)(g_h + (size_t)(ra + 8) * 64 + col) = make_float2(n2, n3);
            *(__half2*)(As + lra * AS_STRIDE + col)       = __floats2half2_rn(n0, n1);
            *(__half2*)(As + (lra + 8) * AS_STRIDE + col) = __floats2half2_rn(n2, n3);
        } else {
            if (ra < NATOMS) {
                float* addr = grf + (size_t)ba * 64 + col;
                asm volatile("red.global.add.v2.f32 [%0], {%1,%2};"
                             :: "l"(addr), "f"(n0), "f"(n1) : "memory");
            }
            if (ra + 8 < NATOMS) {
                float* addr = grf + (size_t)bb * 64 + col;
                asm volatile("red.global.add.v2.f32 [%0], {%1,%2};"
                             :: "l"(addr), "f"(n2), "f"(n3) : "memory");
            }
        }
    }

    // ---- GEMM3 (next cf1): hx = hn @ W3 ----
    if (FUSE_NEXT) {
        __syncthreads();
        stage_w16(Bs, W3, tid);
        __syncthreads();
        zero_d(d);
        mma_gemm(As, Bs, w, lane, d);
        #pragma unroll
        for (int j = 0; j < 8; j++) {
            int col = 8 * j + 2 * tq;
            if (ra < NATOMS)
                *(__half2*)(g_hxh + (size_t)ra * 64 + col) = __floats2half2_rn(d[j][0], d[j][1]);
            if (ra + 8 < NATOMS)
                *(__half2*)(g_hxh + (size_t)(ra + 8) * 64 + col) = __floats2half2_rn(d[j][2], d[j][3]);
        }
    }
}

// ---------------- output head -------------------------------------------------------
__global__ __launch_bounds__(256) void k_head(
    const float* __restrict__ W1, const float* __restrict__ B1,
    const float* __restrict__ W2, const float* __restrict__ B2,
    float* __restrict__ out)
{
    __shared__ float w1s[64 * 32];
    __shared__ float w2s[32];
    __shared__ float b1s[32];
    for (int i = threadIdx.x; i < 2048; i += 256) w1s[i] = W1[i];
    if (threadIdx.x < 32) { w2s[threadIdx.x] = W2[threadIdx.x]; b1s[threadIdx.x] = B1[threadIdx.x]; }
    __syncthreads();
    int g = threadIdx.x;
    if (g >= NGRAPH) return;
    const float* grf = gr_p();
    float gv[64];
    #pragma unroll 16
    for (int k = 0; k < 64; k++) gv[k] = grf[g * 64 + k];
    float o = B2[0];
    #pragma unroll 4
    for (int j = 0; j < 32; j++) {
        float a = b1s[j];
        #pragma unroll 16
        for (int k = 0; k < 64; k++) a += gv[k] * w1s[k * 32 + j];
        o += fmaxf(a, 0.0f) * w2s[j];
    }
    out[g] = o;
}

// ---------------- launcher ------------------------------------------------------------
extern "C" void kernel_launch(void* const* d_in, const int* in_sizes, int n_in,
                              void* d_out, int out_size) {
    const int*   z      = (const int*)  d_in[0];
    const float* pos    = (const float*)d_in[1];
    const int*   batch  = (const int*)  d_in[2];
    const int*   ei     = (const int*)  d_in[3];
    const float* emb    = (const float*)d_in[4];
    const float* mlp_w1 = (const float*)d_in[5];
    const float* mlp_b1 = (const float*)d_in[6];
    const float* mlp_w2 = (const float*)d_in[7];
    const float* mlp_b2 = (const float*)d_in[8];
    const float* cf1_w  = (const float*)d_in[9];
    const float* cf2_w  = (const float*)d_in[10];
    const float* cf2_b  = (const float*)d_in[11];
    const float* lin_w  = (const float*)d_in[12];
    const float* lin_b  = (const float*)d_in[13];
    const float* out1_w = (const float*)d_in[14];
    const float* out1_b = (const float*)d_in[15];
    const float* out2_w = (const float*)d_in[16];
    const float* out2_b = (const float*)d_in[17];
    float* out = (float*)d_out;

    // single memset zeroes hist counts + scan flags + graph accumulator
    void* zp = nullptr;
    cudaGetSymbolAddress(&zp, g_base);
    cudaMemsetAsync(zp, 0, ZBASE_INTS * sizeof(int));

    // independent work first (also positions k_agg as the ncu-profiled launch)
    k_table    <<<NB * (MTAB / 32), 64>>>(mlp_w1, mlp_b1, mlp_w2, mlp_b2);
    k_embed_cf1<<<GEMM_GRID, 256>>>(z, emb, cf1_w);
    k_hist     <<<(NEDGE / 4 + 255) / 256, 256>>>(pos, ei);
    k_scan     <<<NSCANB, 1024>>>();
    k_scatter  <<<(NEDGE / 4 + 255) / 256, 256>>>(ei);

    for (int t = 0; t < NB; t++) {
        k_agg<<<(NATOMS + 7) / 8, 256>>>(t);
        const float* w1 = cf2_w + (size_t)t * 64 * 64;
        const float* b1 = cf2_b + (size_t)t * 64;
        const float* w2 = lin_w + (size_t)t * 64 * 64;
        const float* b2 = lin_b + (size_t)t * 64;
        if (t + 1 < NB)
            k_cf2lin<true><<<GEMM_GRID, 256>>>(w1, b1, w2, b2,
                cf1_w + (size_t)(t + 1) * 64 * 64, batch);
        else
            k_cf2lin<false><<<GEMM_GRID, 256>>>(w1, b1, w2, b2, nullptr, batch);
    }

    k_head<<<1, 256>>>(out1_w, out1_b, out2_w, out2_b, out);
}

// round 15
// speedup vs baseline: 1.1850x; 1.1850x over previous
#include <cuda_runtime.h>
#include <cuda_fp16.h>
#include <math.h>

#define NATOMS  50000
#define NEDGE   1600000
#define NGRAPH  250
#define HDIM    64
#define NGAUSS  50
#define NB      3
#define MTAB    8192
#define KBITS   13
#define TABMAX  8.6700f
#define TABSCALE ((float)(MTAB - 1) / TABMAX)
#define TABSTEP  (TABMAX / (float)(MTAB - 1))
#define NSCANB  49

#define RPB        128
#define GEMM_GRID  ((NATOMS + RPB - 1) / RPB)
#define AS_STRIDE  72          // halves; 144B row pitch -> conflict-free LDSM

// ---------------- scratch ----------------------------------------------------
// g_base = [g_cnt: NATOMS ints][g_gr: NGRAPH*HDIM floats] — one memset
#define ZBASE_INTS (NATOMS + NGRAPH * HDIM)
__device__ int       g_base[ZBASE_INTS];
__device__ int       g_bsum[64];
__device__ __half    g_tabh[NB * MTAB * HDIM];
__device__ float     g_h[NATOMS * HDIM];
__device__ __half    g_hxh[NATOMS * HDIM];
__device__ __half    g_aggh[NATOMS * HDIM];
__device__ int       g_rp[NATOMS + 1];
__device__ int       g_rank[NEDGE];
__device__ unsigned  g_tmp[NEDGE];              // packed (src,knot) in edge order
__device__ unsigned  g_src[NEDGE];              // packed, dst-sorted

__device__ __forceinline__ int*   cnt_p() { return g_base; }
__device__ __forceinline__ float* gr_p()  { return (float*)(g_base + NATOMS); }

__device__ __forceinline__ float ssp(float v) {
    return fmaxf(v, 0.0f) + log1pf(expf(-fabsf(v))) - 0.6931471805599453f;
}

__device__ __forceinline__ unsigned h2u(__half2 h) {
    unsigned u;
    asm("mov.b32 %0,%1;" : "=r"(u) : "r"(*(unsigned*)&h));
    return u;
}

// ---------------- mma.sync helpers ---------------------------------------------
__device__ __forceinline__ void ldmatrix_x4(unsigned& r0, unsigned& r1,
                                            unsigned& r2, unsigned& r3, unsigned addr) {
    asm volatile("ldmatrix.sync.aligned.m8n8.x4.shared.b16 {%0,%1,%2,%3},[%4];"
                 : "=r"(r0), "=r"(r1), "=r"(r2), "=r"(r3) : "r"(addr));
}
__device__ __forceinline__ void ldmatrix_x2_trans(unsigned& r0, unsigned& r1, unsigned addr) {
    asm volatile("ldmatrix.sync.aligned.m8n8.x2.trans.shared.b16 {%0,%1},[%2];"
                 : "=r"(r0), "=r"(r1) : "r"(addr));
}
__device__ __forceinline__ void mma16816(float& d0, float& d1, float& d2, float& d3,
                                         unsigned a0, unsigned a1, unsigned a2, unsigned a3,
                                         unsigned b0, unsigned b1) {
    asm volatile("mma.sync.aligned.m16n8k16.row.col.f32.f16.f16.f32 "
                 "{%0,%1,%2,%3},{%4,%5,%6,%7},{%8,%9},{%0,%1,%2,%3};"
                 : "+f"(d0), "+f"(d1), "+f"(d2), "+f"(d3)
                 : "r"(a0), "r"(a1), "r"(a2), "r"(a3), "r"(b0), "r"(b1));
}

__device__ __forceinline__ void mma_gemm(const __half* As, const __half* Bs,
                                         int w, int lane, float (&d)[8][4]) {
    unsigned as_base = (unsigned)__cvta_generic_to_shared(As);
    unsigned bs_base = (unsigned)__cvta_generic_to_shared(Bs);
    unsigned a[4][4];
    int arow = 16 * w + (lane & 15);
    int acol = (lane >> 4) * 8;
    #pragma unroll
    for (int ks = 0; ks < 4; ks++) {
        unsigned addr = as_base + ((arow * AS_STRIDE + ks * 16 + acol) << 1);
        ldmatrix_x4(a[ks][0], a[ks][1], a[ks][2], a[ks][3], addr);
    }
    int brow = lane & 15;
    #pragma unroll
    for (int j = 0; j < 8; j++) {
        #pragma unroll
        for (int ks = 0; ks < 4; ks++) {
            unsigned b0, b1;
            unsigned addr = bs_base + (((ks * 16 + brow) * AS_STRIDE + j * 8) << 1);
            ldmatrix_x2_trans(b0, b1, addr);
            mma16816(d[j][0], d[j][1], d[j][2], d[j][3],
                     a[ks][0], a[ks][1], a[ks][2], a[ks][3], b0, b1);
        }
    }
}

__device__ __forceinline__ void zero_d(float (&d)[8][4]) {
    #pragma unroll
    for (int j = 0; j < 8; j++)
        #pragma unroll
        for (int p = 0; p < 4; p++) d[j][p] = 0.0f;
}

__device__ __forceinline__ void stage_a_h16(__half* As, const __half* __restrict__ src,
                                            int r0, int tid) {
    #pragma unroll
    for (int it = 0; it < 4; it++) {
        int idx = (it * 256 + tid) * 8;
        int row = idx >> 6, c = idx & 63;
        int gr = min(r0 + row, NATOMS - 1);
        uint4 v = __ldg((const uint4*)(src + (size_t)gr * 64 + c));
        *(uint4*)(As + row * AS_STRIDE + c) = v;
    }
}

__device__ __forceinline__ void stage_w16(__half* Bs, const float* __restrict__ W, int tid) {
    #pragma unroll
    for (int it = 0; it < 4; it++) {
        int idx = (it * 256 + tid) * 4;
        int row = idx >> 6, c = idx & 63;
        float4 v = __ldg((const float4*)(W + idx));
        uint2 u;
        u.x = h2u(__floats2half2_rn(v.x, v.y));
        u.y = h2u(__floats2half2_rn(v.z, v.w));
        *(uint2*)(Bs + row * AS_STRIDE + c) = u;
    }
}

// ---------------- CSR build ----------------------------------------------------
__global__ void k_hist(const float* __restrict__ pos, const int* __restrict__ ei) {
    int e4 = (blockIdx.x * blockDim.x + threadIdx.x) * 4;
    if (e4 >= NEDGE) return;
    int4 s = __ldg((const int4*)(ei + e4));
    int4 t = __ldg((const int4*)(ei + NEDGE + e4));
    int ss[4] = {s.x, s.y, s.z, s.w};
    int tt[4] = {t.x, t.y, t.z, t.w};
    int4 rk;
    unsigned rec[4];
    #pragma unroll
    for (int i = 0; i < 4; i++) {
        float dx = __ldg(pos + 3 * tt[i] + 0) - __ldg(pos + 3 * ss[i] + 0);
        float dy = __ldg(pos + 3 * tt[i] + 1) - __ldg(pos + 3 * ss[i] + 1);
        float dz = __ldg(pos + 3 * tt[i] + 2) - __ldg(pos + 3 * ss[i] + 2);
        float d = sqrtf(dx * dx + dy * dy + dz * dz);
        int knot = min((int)(d * TABSCALE + 0.5f), MTAB - 1);
        rec[i] = ((unsigned)ss[i] << KBITS) | (unsigned)knot;
    }
    int* cnt = cnt_p();
    rk.x = atomicAdd(&cnt[tt[0]], 1);
    rk.y = atomicAdd(&cnt[tt[1]], 1);
    rk.z = atomicAdd(&cnt[tt[2]], 1);
    rk.w = atomicAdd(&cnt[tt[3]], 1);
    *(int4*)(g_rank + e4) = rk;
    *(uint4*)(g_tmp + e4) = make_uint4(rec[0], rec[1], rec[2], rec[3]);
}

__global__ __launch_bounds__(1024) void k_scan1() {
    __shared__ int wsum[32];
    int tid = threadIdx.x, lane = tid & 31, wid = tid >> 5;
    int i = blockIdx.x * 1024 + tid;
    int v = (i < NATOMS) ? cnt_p()[i] : 0;
    int incl = v;
    #pragma unroll
    for (int off = 1; off < 32; off <<= 1) {
        int n = __shfl_up_sync(0xffffffffu, incl, off);
        if (lane >= off) incl += n;
    }
    if (lane == 31) wsum[wid] = incl;
    __syncthreads();
    if (wid == 0) {
        int wv = wsum[lane];
        int wincl = wv;
        #pragma unroll
        for (int off = 1; off < 32; off <<= 1) {
            int n = __shfl_up_sync(0xffffffffu, wincl, off);
            if (lane >= off) wincl += n;
        }
        wsum[lane] = wincl - wv;
    }
    __syncthreads();
    int excl = wsum[wid] + incl - v;
    if (i < NATOMS) g_rp[i] = excl;
    if (tid == 1023) g_bsum[blockIdx.x] = excl + v;
}

__global__ void k_scan2() {
    __shared__ int ws[2];
    int tid = threadIdx.x, lane = tid & 31;
    int v = (tid < NSCANB) ? g_bsum[tid] : 0;
    int incl = v;
    #pragma unroll
    for (int off = 1; off < 32; off <<= 1) {
        int n = __shfl_up_sync(0xffffffffu, incl, off);
        if (lane >= off) incl += n;
    }
    if (lane == 31) ws[tid >> 5] = incl;
    __syncthreads();
    int add = (tid >= 32) ? ws[0] : 0;
    if (tid < NSCANB) g_bsum[tid] = incl - v + add;
}

__global__ __launch_bounds__(1024) void k_scan3() {
    int i = blockIdx.x * 1024 + threadIdx.x;
    if (i < NATOMS) g_rp[i] += g_bsum[blockIdx.x];
    if (i == 0) g_rp[NATOMS] = NEDGE;
}

__global__ void k_scatter(const int* __restrict__ ei) {
    int e4 = (blockIdx.x * blockDim.x + threadIdx.x) * 4;
    if (e4 >= NEDGE) return;
    int4 t = __ldg((const int4*)(ei + NEDGE + e4));
    int4 rk = *(const int4*)(g_rank + e4);
    uint4 rec = *(const uint4*)(g_tmp + e4);
    g_src[__ldg(&g_rp[t.x]) + rk.x] = rec.x;
    g_src[__ldg(&g_rp[t.y]) + rk.y] = rec.y;
    g_src[__ldg(&g_rp[t.z]) + rk.z] = rec.z;
    g_src[__ldg(&g_rp[t.w]) + rk.w] = rec.w;
}

// ---------------- build Wf(d) table (fp16) -------------------------------------
__global__ __launch_bounds__(64) void k_table(
    const float* __restrict__ w1, const float* __restrict__ b1,
    const float* __restrict__ w2, const float* __restrict__ b2)
{
    __shared__ float w1s[NGAUSS * 64];
    __shared__ float w2s[64 * 64];
    __shared__ float b1s[64], b2s[64];
    __shared__ float rbfs[NGAUSS];
    __shared__ float t1s[64];

    const int KPB = 32;
    int t  = blockIdx.x / (MTAB / KPB);
    int kb = blockIdx.x % (MTAB / KPB);
    int tid = threadIdx.x;

    for (int i = tid; i < NGAUSS * 64; i += 64) w1s[i] = w1[t * NGAUSS * 64 + i];
    for (int i = tid; i < 64 * 64;     i += 64) w2s[i] = w2[t * 64 * 64 + i];
    b1s[tid] = b1[t * 64 + tid];
    b2s[tid] = b2[t * 64 + tid];

    const float step  = 10.0f / 49.0f;
    const float coeff = -0.5f / (step * step);

    for (int kk = 0; kk < KPB; kk++) {
        int knot = kb * KPB + kk;
        float dv = (float)knot * TABSTEP;
        __syncthreads();
        if (tid < NGAUSS) {
            float dd = dv - (float)tid * step;
            rbfs[tid] = expf(coeff * dd * dd);
        }
        __syncthreads();
        float a = b1s[tid];
        #pragma unroll 10
        for (int j = 0; j < NGAUSS; j++) a += rbfs[j] * w1s[j * 64 + tid];
        t1s[tid] = ssp(a);
        __syncthreads();
        float a2 = b2s[tid];
        #pragma unroll 16
        for (int k = 0; k < 64; k++) a2 += t1s[k] * w2s[k * 64 + tid];
        float C = 0.5f * (cosf(dv * 0.31415926535897931f) + 1.0f);
        g_tabh[((size_t)t * MTAB + knot) * 64 + tid] = __float2half_rn(a2 * C);
    }
}

// ---------------- fused embed + cf1(t=0), tensor-core GEMM ----------------------
__global__ __launch_bounds__(256) void k_embed_cf1(
    const int* __restrict__ z, const float* __restrict__ emb,
    const float* __restrict__ W)
{
    __shared__ __half As[128 * AS_STRIDE];
    __shared__ __half Bs[64 * AS_STRIDE];
    int tid = threadIdx.x, lane = tid & 31, w = tid >> 5;
    int r0 = blockIdx.x * RPB;

    #pragma unroll
    for (int it = 0; it < 8; it++) {
        int idx = (it * 256 + tid) * 4;
        int row = idx >> 6, c = idx & 63;
        int gr = min(r0 + row, NATOMS - 1);
        int zi = __ldg(z + gr);
        float4 v = __ldg((const float4*)(emb + (size_t)zi * 64 + c));
        if (r0 + row < NATOMS)
            *(float4*)(g_h + (size_t)(r0 + row) * 64 + c) = v;
        uint2 u;
        u.x = h2u(__floats2half2_rn(v.x, v.y));
        u.y = h2u(__floats2half2_rn(v.z, v.w));
        *(uint2*)(As + row * AS_STRIDE + c) = u;
    }
    stage_w16(Bs, W, tid);
    __syncthreads();

    float d[8][4];
    zero_d(d);
    mma_gemm(As, Bs, w, lane, d);

    int g = lane >> 2, t = lane & 3;
    int ra = r0 + 16 * w + g;
    #pragma unroll
    for (int j = 0; j < 8; j++) {
        int col = 8 * j + 2 * t;
        if (ra < NATOMS)
            *(__half2*)(g_hxh + (size_t)ra * 64 + col) = __floats2half2_rn(d[j][0], d[j][1]);
        if (ra + 8 < NATOMS)
            *(__half2*)(g_hxh + (size_t)(ra + 8) * 64 + col) = __floats2half2_rn(d[j][2], d[j][3]);
    }
}

// ---------------- gather-aggregate (fp16 output; one warp per node) --------------
__device__ __forceinline__ void agg_acc(uint4 tv, uint4 hv, float* a) {
    __half2 p0 = __hmul2(*(__half2*)&tv.x, *(__half2*)&hv.x);
    __half2 p1 = __hmul2(*(__half2*)&tv.y, *(__half2*)&hv.y);
    __half2 p2 = __hmul2(*(__half2*)&tv.z, *(__half2*)&hv.z);
    __half2 p3 = __hmul2(*(__half2*)&tv.w, *(__half2*)&hv.w);
    float2 f0 = __half22float2(p0);
    float2 f1 = __half22float2(p1);
    float2 f2 = __half22float2(p2);
    float2 f3 = __half22float2(p3);
    a[0] += f0.x; a[1] += f0.y;
    a[2] += f1.x; a[3] += f1.y;
    a[4] += f2.x; a[5] += f2.y;
    a[6] += f3.x; a[7] += f3.y;
}

__global__ __launch_bounds__(256) void k_agg(int t) {
    int node = blockIdx.x * 8 + (threadIdx.x >> 5);
    if (node >= NATOMS) return;
    int lane = threadIdx.x & 31;
    int grp  = lane >> 3;
    int fl   = lane & 7;
    int beg = __ldg(&g_rp[node]), end = __ldg(&g_rp[node + 1]);

    float a[8];
    #pragma unroll
    for (int i = 0; i < 8; i++) a[i] = 0.0f;
    const __half* tb = g_tabh + (size_t)t * MTAB * 64;

    int base = beg;
    for (; base + 32 <= end; base += 32) {
        unsigned rec = __ldg(&g_src[base + lane]);
        #pragma unroll
        for (int j = 0; j < 32; j += 8) {
            unsigned rA = __shfl_sync(0xffffffffu, rec, j + grp);
            unsigned rB = __shfl_sync(0xffffffffu, rec, j + 4 + grp);
            uint4 tA = __ldg((const uint4*)(tb + (size_t)(rA & (MTAB - 1)) * 64) + fl);
            uint4 tB = __ldg((const uint4*)(tb + (size_t)(rB & (MTAB - 1)) * 64) + fl);
            uint4 hA = __ldg((const uint4*)(g_hxh + (size_t)(rA >> KBITS) * 64) + fl);
            uint4 hB = __ldg((const uint4*)(g_hxh + (size_t)(rB >> KBITS) * 64) + fl);
            agg_acc(tA, hA, a);
            agg_acc(tB, hB, a);
        }
    }
    if (base < end) {
        unsigned rec = 0u;
        if (base + lane < end) rec = __ldg(&g_src[base + lane]);
        int n = end - base;
        for (int j = 0; j < n; j += 4) {
            unsigned r = __shfl_sync(0xffffffffu, rec, j + grp);
            if (j + grp < n) {
                uint4 tv = __ldg((const uint4*)(tb + (size_t)(r & (MTAB - 1)) * 64) + fl);
                uint4 hv = __ldg((const uint4*)(g_hxh + (size_t)(r >> KBITS) * 64) + fl);
                agg_acc(tv, hv, a);
            }
        }
    }

    #pragma unroll
    for (int i = 0; i < 8; i++) {
        a[i] += __shfl_down_sync(0xffffffffu, a[i], 16);
        a[i] += __shfl_down_sync(0xffffffffu, a[i], 8);
    }
    if (grp == 0) {
        uint4 o;
        o.x = h2u(__floats2half2_rn(a[0], a[1]));
        o.y = h2u(__floats2half2_rn(a[2], a[3]));
        o.z = h2u(__floats2half2_rn(a[4], a[5]));
        o.w = h2u(__floats2half2_rn(a[6], a[7]));
        *(uint4*)(g_aggh + (size_t)node * 64 + fl * 8) = o;
    }
}

// ---------------- cf2lin: 3 tensor-core GEMMs; last interaction fuses readout ----
template <bool FUSE_NEXT>
__global__ __launch_bounds__(256) void k_cf2lin(
    const float* __restrict__ W1, const float* __restrict__ B1,
    const float* __restrict__ W2, const float* __restrict__ B2,
    const float* __restrict__ W3, const int* __restrict__ batch)
{
    __shared__ __half As[128 * AS_STRIDE];
    __shared__ __half Bs[64 * AS_STRIDE];
    __shared__ float sbias[64];
    int tid = threadIdx.x, lane = tid & 31, w = tid >> 5;
    int r0 = blockIdx.x * RPB;
    int g = lane >> 2, tq = lane & 3;
    int lra = 16 * w + g;

    // ---- GEMM1: us = ssp(agg @ W1 + B1) ----
    stage_a_h16(As, g_aggh, r0, tid);
    stage_w16(Bs, W1, tid);
    if (tid < 64) sbias[tid] = __ldg(B1 + tid);
    __syncthreads();

    float d[8][4];
    zero_d(d);
    mma_gemm(As, Bs, w, lane, d);

    #pragma unroll
    for (int j = 0; j < 8; j++) {
        int col = 8 * j + 2 * tq;
        float b0v = sbias[col], b1v = sbias[col + 1];
        *(__half2*)(As + lra * AS_STRIDE + col) =
            __floats2half2_rn(ssp(d[j][0] + b0v), ssp(d[j][1] + b1v));
        *(__half2*)(As + (lra + 8) * AS_STRIDE + col) =
            __floats2half2_rn(ssp(d[j][2] + b0v), ssp(d[j][3] + b1v));
    }
    __syncthreads();
    stage_w16(Bs, W2, tid);
    if (tid < 64) sbias[tid] = __ldg(B2 + tid);
    __syncthreads();

    // ---- GEMM2: x = us @ W2 + B2 ; hn = h + x ----
    zero_d(d);
    mma_gemm(As, Bs, w, lane, d);

    int ra = r0 + lra;
    int gra = min(ra, NATOMS - 1), grb = min(ra + 8, NATOMS - 1);
    int ba = 0, bb = 0;
    if (!FUSE_NEXT) {
        ba = __ldg(batch + gra);
        bb = __ldg(batch + grb);
    }
    float* grf = gr_p();
    #pragma unroll
    for (int j = 0; j < 8; j++) {
        int col = 8 * j + 2 * tq;
        float b0v = sbias[col], b1v = sbias[col + 1];
        float2 h0 = *(const float2*)(g_h + (size_t)gra * 64 + col);
        float2 h1 = *(const float2*)(g_h + (size_t)grb * 64 + col);
        float n0 = h0.x + d[j][0] + b0v, n1 = h0.y + d[j][1] + b1v;
        float n2 = h1.x + d[j][2] + b0v, n3 = h1.y + d[j][3] + b1v;
        if (FUSE_NEXT) {
            if (ra < NATOMS)
                *(float2*)(g_h + (size_t)ra * 64 + col) = make_float2(n0, n1);
            if (ra + 8 < NATOMS)
                *(float2*)(g_h + (size_t)(ra + 8) * 64 + col) = make_float2(n2, n3);
            *(__half2*)(As + lra * AS_STRIDE + col)       = __floats2half2_rn(n0, n1);
            *(__half2*)(As + (lra + 8) * AS_STRIDE + col) = __floats2half2_rn(n2, n3);
        } else {
            if (ra < NATOMS) {
                float* addr = grf + (size_t)ba * 64 + col;
                asm volatile("red.global.add.v2.f32 [%0], {%1,%2};"
                             :: "l"(addr), "f"(n0), "f"(n1) : "memory");
            }
            if (ra + 8 < NATOMS) {
                float* addr = grf + (size_t)bb * 64 + col;
                asm volatile("red.global.add.v2.f32 [%0], {%1,%2};"
                             :: "l"(addr), "f"(n2), "f"(n3) : "memory");
            }
        }
    }

    // ---- GEMM3 (next cf1): hx = hn @ W3 ----
    if (FUSE_NEXT) {
        __syncthreads();
        stage_w16(Bs, W3, tid);
        __syncthreads();
        zero_d(d);
        mma_gemm(As, Bs, w, lane, d);
        #pragma unroll
        for (int j = 0; j < 8; j++) {
            int col = 8 * j + 2 * tq;
            if (ra < NATOMS)
                *(__half2*)(g_hxh + (size_t)ra * 64 + col) = __floats2half2_rn(d[j][0], d[j][1]);
            if (ra + 8 < NATOMS)
                *(__half2*)(g_hxh + (size_t)(ra + 8) * 64 + col) = __floats2half2_rn(d[j][2], d[j][3]);
        }
    }
}

// ---------------- output head -------------------------------------------------------
__global__ __launch_bounds__(256) void k_head(
    const float* __restrict__ W1, const float* __restrict__ B1,
    const float* __restrict__ W2, const float* __restrict__ B2,
    float* __restrict__ out)
{
    __shared__ float w1s[64 * 32];
    __shared__ float w2s[32];
    __shared__ float b1s[32];
    for (int i = threadIdx.x; i < 2048; i += 256) w1s[i] = W1[i];
    if (threadIdx.x < 32) { w2s[threadIdx.x] = W2[threadIdx.x]; b1s[threadIdx.x] = B1[threadIdx.x]; }
    __syncthreads();
    int g = threadIdx.x;
    if (g >= NGRAPH) return;
    const float* grf = gr_p();
    float gv[64];
    #pragma unroll 16
    for (int k = 0; k < 64; k++) gv[k] = grf[g * 64 + k];
    float o = B2[0];
    #pragma unroll 4
    for (int j = 0; j < 32; j++) {
        float a = b1s[j];
        #pragma unroll 16
        for (int k = 0; k < 64; k++) a += gv[k] * w1s[k * 32 + j];
        o += fmaxf(a, 0.0f) * w2s[j];
    }
    out[g] = o;
}

// ---------------- launcher ------------------------------------------------------------
extern "C" void kernel_launch(void* const* d_in, const int* in_sizes, int n_in,
                              void* d_out, int out_size) {
    const int*   z      = (const int*)  d_in[0];
    const float* pos    = (const float*)d_in[1];
    const int*   batch  = (const int*)  d_in[2];
    const int*   ei     = (const int*)  d_in[3];
    const float* emb    = (const float*)d_in[4];
    const float* mlp_w1 = (const float*)d_in[5];
    const float* mlp_b1 = (const float*)d_in[6];
    const float* mlp_w2 = (const float*)d_in[7];
    const float* mlp_b2 = (const float*)d_in[8];
    const float* cf1_w  = (const float*)d_in[9];
    const float* cf2_w  = (const float*)d_in[10];
    const float* cf2_b  = (const float*)d_in[11];
    const float* lin_w  = (const float*)d_in[12];
    const float* lin_b  = (const float*)d_in[13];
    const float* out1_w = (const float*)d_in[14];
    const float* out1_b = (const float*)d_in[15];
    const float* out2_w = (const float*)d_in[16];
    const float* out2_b = (const float*)d_in[17];
    float* out = (float*)d_out;

    // single memset zeroes hist counts + graph accumulator
    void* zp = nullptr;
    cudaGetSymbolAddress(&zp, g_base);
    cudaMemsetAsync(zp, 0, ZBASE_INTS * sizeof(int));

    // independent work first
    k_table    <<<NB * (MTAB / 32), 64>>>(mlp_w1, mlp_b1, mlp_w2, mlp_b2);
    k_embed_cf1<<<GEMM_GRID, 256>>>(z, emb, cf1_w);
    k_hist     <<<(NEDGE / 4 + 255) / 256, 256>>>(pos, ei);
    k_scan1    <<<NSCANB, 1024>>>();
    k_scan2    <<<1, 64>>>();
    k_scan3    <<<NSCANB, 1024>>>();
    k_scatter  <<<(NEDGE / 4 + 255) / 256, 256>>>(ei);

    for (int t = 0; t < NB; t++) {
        k_agg<<<(NATOMS + 7) / 8, 256>>>(t);
        const float* w1 = cf2_w + (size_t)t * 64 * 64;
        const float* b1 = cf2_b + (size_t)t * 64;
        const float* w2 = lin_w + (size_t)t * 64 * 64;
        const float* b2 = lin_b + (size_t)t * 64;
        if (t + 1 < NB)
            k_cf2lin<true><<<GEMM_GRID, 256>>>(w1, b1, w2, b2,
                cf1_w + (size_t)(t + 1) * 64 * 64, batch);
        else
            k_cf2lin<false><<<GEMM_GRID, 256>>>(w1, b1, w2, b2, nullptr, batch);
    }

    k_head<<<1, 256>>>(out1_w, out1_b, out2_w, out2_b, out);
}

// round 16
// speedup vs baseline: 1.2398x; 1.0462x over previous
#include <cuda_runtime.h>
#include <cuda_fp16.h>
#include <math.h>

#define NATOMS  50000
#define NEDGE   1600000
#define NGRAPH  250
#define HDIM    64
#define NGAUSS  50
#define NB      3
#define MTAB    512                       // lerp table: 128KB/interaction, L1-resident
#define TABMAX  8.6700f
#define TABSCALE ((float)(MTAB - 1) / TABMAX)
#define TABSTEP  (TABMAX / (float)(MTAB - 1))
#define NSCANB  49

#define RPB        128
#define GEMM_GRID  ((NATOMS + RPB - 1) / RPB)
#define AS_STRIDE  72          // halves; 144B row pitch -> conflict-free LDSM

// ---------------- scratch ----------------------------------------------------
// g_base = [g_cnt: NATOMS ints][g_gr: NGRAPH*HDIM floats] — one memset
#define ZBASE_INTS (NATOMS + NGRAPH * HDIM)
__device__ int       g_base[ZBASE_INTS];
__device__ int       g_bsum[64];
__device__ __half    g_tabp[NB * MTAB * 128];   // paired: [A(64)|D(64)] per knot
__device__ float     g_h[NATOMS * HDIM];
__device__ __half    g_hxh[NATOMS * HDIM];
__device__ __half    g_aggh[NATOMS * HDIM];
__device__ int       g_rp[NATOMS + 1];
__device__ int       g_rank[NEDGE];
__device__ unsigned  g_tmp[NEDGE];              // packed (src:17|knot:9|frac:6)
__device__ unsigned  g_src[NEDGE];              // packed, dst-sorted

__device__ __forceinline__ int*   cnt_p() { return g_base; }
__device__ __forceinline__ float* gr_p()  { return (float*)(g_base + NATOMS); }

__device__ __forceinline__ float ssp(float v) {
    return fmaxf(v, 0.0f) + log1pf(expf(-fabsf(v))) - 0.6931471805599453f;
}

__device__ __forceinline__ unsigned h2u(__half2 h) {
    unsigned u;
    asm("mov.b32 %0,%1;" : "=r"(u) : "r"(*(unsigned*)&h));
    return u;
}

// L1 evict-last vector load (table rows: high-reuse, keep resident)
__device__ __forceinline__ uint4 ldg_el(const void* p) {
    uint4 v;
    asm volatile("ld.global.nc.L1::evict_last.v4.u32 {%0,%1,%2,%3},[%4];"
                 : "=r"(v.x), "=r"(v.y), "=r"(v.z), "=r"(v.w) : "l"(p));
    return v;
}

// ---------------- mma.sync helpers ---------------------------------------------
__device__ __forceinline__ void ldmatrix_x4(unsigned& r0, unsigned& r1,
                                            unsigned& r2, unsigned& r3, unsigned addr) {
    asm volatile("ldmatrix.sync.aligned.m8n8.x4.shared.b16 {%0,%1,%2,%3},[%4];"
                 : "=r"(r0), "=r"(r1), "=r"(r2), "=r"(r3) : "r"(addr));
}
__device__ __forceinline__ void ldmatrix_x2_trans(unsigned& r0, unsigned& r1, unsigned addr) {
    asm volatile("ldmatrix.sync.aligned.m8n8.x2.trans.shared.b16 {%0,%1},[%2];"
                 : "=r"(r0), "=r"(r1) : "r"(addr));
}
__device__ __forceinline__ void mma16816(float& d0, float& d1, float& d2, float& d3,
                                         unsigned a0, unsigned a1, unsigned a2, unsigned a3,
                                         unsigned b0, unsigned b1) {
    asm volatile("mma.sync.aligned.m16n8k16.row.col.f32.f16.f16.f32 "
                 "{%0,%1,%2,%3},{%4,%5,%6,%7},{%8,%9},{%0,%1,%2,%3};"
                 : "+f"(d0), "+f"(d1), "+f"(d2), "+f"(d3)
                 : "r"(a0), "r"(a1), "r"(a2), "r"(a3), "r"(b0), "r"(b1));
}

__device__ __forceinline__ void mma_gemm(const __half* As, const __half* Bs,
                                         int w, int lane, float (&d)[8][4]) {
    unsigned as_base = (unsigned)__cvta_generic_to_shared(As);
    unsigned bs_base = (unsigned)__cvta_generic_to_shared(Bs);
    unsigned a[4][4];
    int arow = 16 * w + (lane & 15);
    int acol = (lane >> 4) * 8;
    #pragma unroll
    for (int ks = 0; ks < 4; ks++) {
        unsigned addr = as_base + ((arow * AS_STRIDE + ks * 16 + acol) << 1);
        ldmatrix_x4(a[ks][0], a[ks][1], a[ks][2], a[ks][3], addr);
    }
    int brow = lane & 15;
    #pragma unroll
    for (int j = 0; j < 8; j++) {
        #pragma unroll
        for (int ks = 0; ks < 4; ks++) {
            unsigned b0, b1;
            unsigned addr = bs_base + (((ks * 16 + brow) * AS_STRIDE + j * 8) << 1);
            ldmatrix_x2_trans(b0, b1, addr);
            mma16816(d[j][0], d[j][1], d[j][2], d[j][3],
                     a[ks][0], a[ks][1], a[ks][2], a[ks][3], b0, b1);
        }
    }
}

__device__ __forceinline__ void zero_d(float (&d)[8][4]) {
    #pragma unroll
    for (int j = 0; j < 8; j++)
        #pragma unroll
        for (int p = 0; p < 4; p++) d[j][p] = 0.0f;
}

__device__ __forceinline__ void stage_a_h16(__half* As, const __half* __restrict__ src,
                                            int r0, int tid) {
    #pragma unroll
    for (int it = 0; it < 4; it++) {
        int idx = (it * 256 + tid) * 8;
        int row = idx >> 6, c = idx & 63;
        int gr = min(r0 + row, NATOMS - 1);
        uint4 v = __ldg((const uint4*)(src + (size_t)gr * 64 + c));
        *(uint4*)(As + row * AS_STRIDE + c) = v;
    }
}

__device__ __forceinline__ void stage_w16(__half* Bs, const float* __restrict__ W, int tid) {
    #pragma unroll
    for (int it = 0; it < 4; it++) {
        int idx = (it * 256 + tid) * 4;
        int row = idx >> 6, c = idx & 63;
        float4 v = __ldg((const float4*)(W + idx));
        uint2 u;
        u.x = h2u(__floats2half2_rn(v.x, v.y));
        u.y = h2u(__floats2half2_rn(v.z, v.w));
        *(uint2*)(Bs + row * AS_STRIDE + c) = u;
    }
}

// ---------------- CSR build ----------------------------------------------------
__global__ void k_hist(const float* __restrict__ pos, const int* __restrict__ ei) {
    int e4 = (blockIdx.x * blockDim.x + threadIdx.x) * 4;
    if (e4 >= NEDGE) return;
    int4 s = __ldg((const int4*)(ei + e4));
    int4 t = __ldg((const int4*)(ei + NEDGE + e4));
    int ss[4] = {s.x, s.y, s.z, s.w};
    int tt[4] = {t.x, t.y, t.z, t.w};
    int4 rk;
    unsigned rec[4];
    #pragma unroll
    for (int i = 0; i < 4; i++) {
        float dx = __ldg(pos + 3 * tt[i] + 0) - __ldg(pos + 3 * ss[i] + 0);
        float dy = __ldg(pos + 3 * tt[i] + 1) - __ldg(pos + 3 * ss[i] + 1);
        float dz = __ldg(pos + 3 * tt[i] + 2) - __ldg(pos + 3 * ss[i] + 2);
        float d = sqrtf(dx * dx + dy * dy + dz * dz);
        float x = fminf(d * TABSCALE, (float)(MTAB - 1) - 1e-4f);
        int kn = (int)x;
        int fr = (int)((x - (float)kn) * 64.0f);      // 0..63
        rec[i] = ((unsigned)ss[i] << 15) | ((unsigned)kn << 6) | (unsigned)fr;
    }
    int* cnt = cnt_p();
    rk.x = atomicAdd(&cnt[tt[0]], 1);
    rk.y = atomicAdd(&cnt[tt[1]], 1);
    rk.z = atomicAdd(&cnt[tt[2]], 1);
    rk.w = atomicAdd(&cnt[tt[3]], 1);
    *(int4*)(g_rank + e4) = rk;
    *(uint4*)(g_tmp + e4) = make_uint4(rec[0], rec[1], rec[2], rec[3]);
}

__global__ __launch_bounds__(1024) void k_scan1() {
    __shared__ int wsum[32];
    int tid = threadIdx.x, lane = tid & 31, wid = tid >> 5;
    int i = blockIdx.x * 1024 + tid;
    int v = (i < NATOMS) ? cnt_p()[i] : 0;
    int incl = v;
    #pragma unroll
    for (int off = 1; off < 32; off <<= 1) {
        int n = __shfl_up_sync(0xffffffffu, incl, off);
        if (lane >= off) incl += n;
    }
    if (lane == 31) wsum[wid] = incl;
    __syncthreads();
    if (wid == 0) {
        int wv = wsum[lane];
        int wincl = wv;
        #pragma unroll
        for (int off = 1; off < 32; off <<= 1) {
            int n = __shfl_up_sync(0xffffffffu, wincl, off);
            if (lane >= off) wincl += n;
        }
        wsum[lane] = wincl - wv;
    }
    __syncthreads();
    int excl = wsum[wid] + incl - v;
    if (i < NATOMS) g_rp[i] = excl;
    if (tid == 1023) g_bsum[blockIdx.x] = excl + v;
}

__global__ void k_scan2() {
    __shared__ int ws[2];
    int tid = threadIdx.x, lane = tid & 31;
    int v = (tid < NSCANB) ? g_bsum[tid] : 0;
    int incl = v;
    #pragma unroll
    for (int off = 1; off < 32; off <<= 1) {
        int n = __shfl_up_sync(0xffffffffu, incl, off);
        if (lane >= off) incl += n;
    }
    if (lane == 31) ws[tid >> 5] = incl;
    __syncthreads();
    int add = (tid >= 32) ? ws[0] : 0;
    if (tid < NSCANB) g_bsum[tid] = incl - v + add;
}

__global__ __launch_bounds__(1024) void k_scan3() {
    int i = blockIdx.x * 1024 + threadIdx.x;
    if (i < NATOMS) g_rp[i] += g_bsum[blockIdx.x];
    if (i == 0) g_rp[NATOMS] = NEDGE;
}

__global__ void k_scatter(const int* __restrict__ ei) {
    int e4 = (blockIdx.x * blockDim.x + threadIdx.x) * 4;
    if (e4 >= NEDGE) return;
    int4 t = __ldg((const int4*)(ei + NEDGE + e4));
    int4 rk = *(const int4*)(g_rank + e4);
    uint4 rec = *(const uint4*)(g_tmp + e4);
    g_src[__ldg(&g_rp[t.x]) + rk.x] = rec.x;
    g_src[__ldg(&g_rp[t.y]) + rk.y] = rec.y;
    g_src[__ldg(&g_rp[t.z]) + rk.z] = rec.z;
    g_src[__ldg(&g_rp[t.w]) + rk.w] = rec.w;
}

// ---------------- build paired lerp table: per knot [A(64)|D(64)] fp16 ----------
__global__ __launch_bounds__(64) void k_table(
    const float* __restrict__ w1, const float* __restrict__ b1,
    const float* __restrict__ w2, const float* __restrict__ b2)
{
    __shared__ float w1s[NGAUSS * 64];
    __shared__ float w2s[64 * 64];
    __shared__ float b1s[64], b2s[64];
    __shared__ float rbfs[NGAUSS];
    __shared__ float t1s[64];

    const int KPB = 32;
    int t  = blockIdx.x / (MTAB / KPB);
    int kb = blockIdx.x % (MTAB / KPB);
    int tid = threadIdx.x;

    for (int i = tid; i < NGAUSS * 64; i += 64) w1s[i] = w1[t * NGAUSS * 64 + i];
    for (int i = tid; i < 64 * 64;     i += 64) w2s[i] = w2[t * 64 * 64 + i];
    b1s[tid] = b1[t * 64 + tid];
    b2s[tid] = b2[t * 64 + tid];

    const float step  = 10.0f / 49.0f;
    const float coeff = -0.5f / (step * step);

    float prevv = 0.0f;
    for (int kk = 0; kk <= KPB; kk++) {            // KPB+1 evals -> KPB (A,D) rows
        int knot = kb * KPB + kk;
        float dv = (float)knot * TABSTEP;
        __syncthreads();
        if (tid < NGAUSS) {
            float dd = dv - (float)tid * step;
            rbfs[tid] = expf(coeff * dd * dd);
        }
        __syncthreads();
        float a = b1s[tid];
        #pragma unroll 10
        for (int j = 0; j < NGAUSS; j++) a += rbfs[j] * w1s[j * 64 + tid];
        t1s[tid] = ssp(a);
        __syncthreads();
        float a2 = b2s[tid];
        #pragma unroll 16
        for (int k = 0; k < 64; k++) a2 += t1s[k] * w2s[k * 64 + tid];
        float C = 0.5f * (cosf(dv * 0.31415926535897931f) + 1.0f);
        float cur = a2 * C;
        if (kk > 0) {
            size_t rowb = ((size_t)t * MTAB + (knot - 1)) * 128;
            g_tabp[rowb + tid]      = __float2half_rn(prevv);
            g_tabp[rowb + 64 + tid] = __float2half_rn(cur - prevv);
        }
        prevv = cur;
    }
}

// ---------------- fused embed + cf1(t=0), tensor-core GEMM ----------------------
__global__ __launch_bounds__(256) void k_embed_cf1(
    const int* __restrict__ z, const float* __restrict__ emb,
    const float* __restrict__ W)
{
    __shared__ __half As[128 * AS_STRIDE];
    __shared__ __half Bs[64 * AS_STRIDE];
    int tid = threadIdx.x, lane = tid & 31, w = tid >> 5;
    int r0 = blockIdx.x * RPB;

    #pragma unroll
    for (int it = 0; it < 8; it++) {
        int idx = (it * 256 + tid) * 4;
        int row = idx >> 6, c = idx & 63;
        int gr = min(r0 + row, NATOMS - 1);
        int zi = __ldg(z + gr);
        float4 v = __ldg((const float4*)(emb + (size_t)zi * 64 + c));
        if (r0 + row < NATOMS)
            *(float4*)(g_h + (size_t)(r0 + row) * 64 + c) = v;
        uint2 u;
        u.x = h2u(__floats2half2_rn(v.x, v.y));
        u.y = h2u(__floats2half2_rn(v.z, v.w));
        *(uint2*)(As + row * AS_STRIDE + c) = u;
    }
    stage_w16(Bs, W, tid);
    __syncthreads();

    float d[8][4];
    zero_d(d);
    mma_gemm(As, Bs, w, lane, d);

    int g = lane >> 2, t = lane & 3;
    int ra = r0 + 16 * w + g;
    #pragma unroll
    for (int j = 0; j < 8; j++) {
        int col = 8 * j + 2 * t;
        if (ra < NATOMS)
            *(__half2*)(g_hxh + (size_t)ra * 64 + col) = __floats2half2_rn(d[j][0], d[j][1]);
        if (ra + 8 < NATOMS)
            *(__half2*)(g_hxh + (size_t)(ra + 8) * 64 + col) = __floats2half2_rn(d[j][2], d[j][3]);
    }
}

// ---------------- gather-aggregate: lerp table, L1-resident ----------------------
__device__ __forceinline__ void agg_lerp(const __half* __restrict__ tb,
                                         unsigned r, int fl, float* a) {
    unsigned src  = r >> 15;
    unsigned kn   = (r >> 6) & (MTAB - 1);
    __half2 w2 = __float2half2_rn((float)(r & 63) * 0.015625f);
    const __half* row = tb + (size_t)kn * 128;
    uint4 av = ldg_el(row + fl * 8);
    uint4 dv = ldg_el(row + 64 + fl * 8);
    uint4 hv = __ldg((const uint4*)(g_hxh + (size_t)src * 64) + fl);
    __half2 v0 = __hfma2(w2, *(__half2*)&dv.x, *(__half2*)&av.x);
    __half2 v1 = __hfma2(w2, *(__half2*)&dv.y, *(__half2*)&av.y);
    __half2 v2 = __hfma2(w2, *(__half2*)&dv.z, *(__half2*)&av.z);
    __half2 v3 = __hfma2(w2, *(__half2*)&dv.w, *(__half2*)&av.w);
    float2 f0 = __half22float2(__hmul2(v0, *(__half2*)&hv.x));
    float2 f1 = __half22float2(__hmul2(v1, *(__half2*)&hv.y));
    float2 f2 = __half22float2(__hmul2(v2, *(__half2*)&hv.z));
    float2 f3 = __half22float2(__hmul2(v3, *(__half2*)&hv.w));
    a[0] += f0.x; a[1] += f0.y;
    a[2] += f1.x; a[3] += f1.y;
    a[4] += f2.x; a[5] += f2.y;
    a[6] += f3.x; a[7] += f3.y;
}

__global__ __launch_bounds__(256) void k_agg(int t) {
    int node = blockIdx.x * 8 + (threadIdx.x >> 5);
    if (node >= NATOMS) return;
    int lane = threadIdx.x & 31;
    int grp  = lane >> 3;
    int fl   = lane & 7;
    int beg = __ldg(&g_rp[node]), end = __ldg(&g_rp[node + 1]);

    float a[8];
    #pragma unroll
    for (int i = 0; i < 8; i++) a[i] = 0.0f;
    const __half* tb = g_tabp + (size_t)t * MTAB * 128;

    int base = beg;
    for (; base + 32 <= end; base += 32) {
        unsigned rec = __ldg(&g_src[base + lane]);
        #pragma unroll
        for (int j = 0; j < 32; j += 8) {
            unsigned rA = __shfl_sync(0xffffffffu, rec, j + grp);
            unsigned rB = __shfl_sync(0xffffffffu, rec, j + 4 + grp);
            agg_lerp(tb, rA, fl, a);
            agg_lerp(tb, rB, fl, a);
        }
    }
    if (base < end) {
        unsigned rec = 0u;
        if (base + lane < end) rec = __ldg(&g_src[base + lane]);
        int n = end - base;
        for (int j = 0; j < n; j += 4) {
            unsigned r = __shfl_sync(0xffffffffu, rec, j + grp);
            if (j + grp < n) agg_lerp(tb, r, fl, a);
        }
    }

    #pragma unroll
    for (int i = 0; i < 8; i++) {
        a[i] += __shfl_down_sync(0xffffffffu, a[i], 16);
        a[i] += __shfl_down_sync(0xffffffffu, a[i], 8);
    }
    if (grp == 0) {
        uint4 o;
        o.x = h2u(__floats2half2_rn(a[0], a[1]));
        o.y = h2u(__floats2half2_rn(a[2], a[3]));
        o.z = h2u(__floats2half2_rn(a[4], a[5]));
        o.w = h2u(__floats2half2_rn(a[6], a[7]));
        *(uint4*)(g_aggh + (size_t)node * 64 + fl * 8) = o;
    }
}

// ---------------- cf2lin: 3 tensor-core GEMMs; last interaction fuses readout ----
template <bool FUSE_NEXT>
__global__ __launch_bounds__(256) void k_cf2lin(
    const float* __restrict__ W1, const float* __restrict__ B1,
    const float* __restrict__ W2, const float* __restrict__ B2,
    const float* __restrict__ W3, const int* __restrict__ batch)
{
    __shared__ __half As[128 * AS_STRIDE];
    __shared__ __half Bs[64 * AS_STRIDE];
    __shared__ float sbias[64];
    int tid = threadIdx.x, lane = tid & 31, w = tid >> 5;
    int r0 = blockIdx.x * RPB;
    int g = lane >> 2, tq = lane & 3;
    int lra = 16 * w + g;

    // ---- GEMM1: us = ssp(agg @ W1 + B1) ----
    stage_a_h16(As, g_aggh, r0, tid);
    stage_w16(Bs, W1, tid);
    if (tid < 64) sbias[tid] = __ldg(B1 + tid);
    __syncthreads();

    float d[8][4];
    zero_d(d);
    mma_gemm(As, Bs, w, lane, d);

    #pragma unroll
    for (int j = 0; j < 8; j++) {
        int col = 8 * j + 2 * tq;
        float b0v = sbias[col], b1v = sbias[col + 1];
        *(__half2*)(As + lra * AS_STRIDE + col) =
            __floats2half2_rn(ssp(d[j][0] + b0v), ssp(d[j][1] + b1v));
        *(__half2*)(As + (lra + 8) * AS_STRIDE + col) =
            __floats2half2_rn(ssp(d[j][2] + b0v), ssp(d[j][3] + b1v));
    }
    __syncthreads();
    stage_w16(Bs, W2, tid);
    if (tid < 64) sbias[tid] = __ldg(B2 + tid);
    __syncthreads();

    // ---- GEMM2: x = us @ W2 + B2 ; hn = h + x ----
    zero_d(d);
    mma_gemm(As, Bs, w, lane, d);

    int ra = r0 + lra;
    int gra = min(ra, NATOMS - 1), grb = min(ra + 8, NATOMS - 1);
    int ba = 0, bb = 0;
    if (!FUSE_NEXT) {
        ba = __ldg(batch + gra);
        bb = __ldg(batch + grb);
    }
    float* grf = gr_p();
    #pragma unroll
    for (int j = 0; j < 8; j++) {
        int col = 8 * j + 2 * tq;
        float b0v = sbias[col], b1v = sbias[col + 1];
        float2 h0 = *(const float2*)(g_h + (size_t)gra * 64 + col);
        float2 h1 = *(const float2*)(g_h + (size_t)grb * 64 + col);
        float n0 = h0.x + d[j][0] + b0v, n1 = h0.y + d[j][1] + b1v;
        float n2 = h1.x + d[j][2] + b0v, n3 = h1.y + d[j][3] + b1v;
        if (FUSE_NEXT) {
            if (ra < NATOMS)
                *(float2*)(g_h + (size_t)ra * 64 + col) = make_float2(n0, n1);
            if (ra + 8 < NATOMS)
                *(float2*)(g_h + (size_t)(ra + 8) * 64 + col) = make_float2(n2, n3);
            *(__half2*)(As + lra * AS_STRIDE + col)       = __floats2half2_rn(n0, n1);
            *(__half2*)(As + (lra + 8) * AS_STRIDE + col) = __floats2half2_rn(n2, n3);
        } else {
            if (ra < NATOMS) {
                float* addr = grf + (size_t)ba * 64 + col;
                asm volatile("red.global.add.v2.f32 [%0], {%1,%2};"
                             :: "l"(addr), "f"(n0), "f"(n1) : "memory");
            }
            if (ra + 8 < NATOMS) {
                float* addr = grf + (size_t)bb * 64 + col;
                asm volatile("red.global.add.v2.f32 [%0], {%1,%2};"
                             :: "l"(addr), "f"(n2), "f"(n3) : "memory");
            }
        }
    }

    // ---- GEMM3 (next cf1): hx = hn @ W3 ----
    if (FUSE_NEXT) {
        __syncthreads();
        stage_w16(Bs, W3, tid);
        __syncthreads();
        zero_d(d);
        mma_gemm(As, Bs, w, lane, d);
        #pragma unroll
        for (int j = 0; j < 8; j++) {
            int col = 8 * j + 2 * tq;
            if (ra < NATOMS)
                *(__half2*)(g_hxh + (size_t)ra * 64 + col) = __floats2half2_rn(d[j][0], d[j][1]);
            if (ra + 8 < NATOMS)
                *(__half2*)(g_hxh + (size_t)(ra + 8) * 64 + col) = __floats2half2_rn(d[j][2], d[j][3]);
        }
    }
}

// ---------------- output head -------------------------------------------------------
__global__ __launch_bounds__(256) void k_head(
    const float* __restrict__ W1, const float* __restrict__ B1,
    const float* __restrict__ W2, const float* __restrict__ B2,
    float* __restrict__ out)
{
    __shared__ float w1s[64 * 32];
    __shared__ float w2s[32];
    __shared__ float b1s[32];
    for (int i = threadIdx.x; i < 2048; i += 256) w1s[i] = W1[i];
    if (threadIdx.x < 32) { w2s[threadIdx.x] = W2[threadIdx.x]; b1s[threadIdx.x] = B1[threadIdx.x]; }
    __syncthreads();
    int g = threadIdx.x;
    if (g >= NGRAPH) return;
    const float* grf = gr_p();
    float gv[64];
    #pragma unroll 16
    for (int k = 0; k < 64; k++) gv[k] = grf[g * 64 + k];
    float o = B2[0];
    #pragma unroll 4
    for (int j = 0; j < 32; j++) {
        float a = b1s[j];
        #pragma unroll 16
        for (int k = 0; k < 64; k++) a += gv[k] * w1s[k * 32 + j];
        o += fmaxf(a, 0.0f) * w2s[j];
    }
    out[g] = o;
}

// ---------------- launcher ------------------------------------------------------------
extern "C" void kernel_launch(void* const* d_in, const int* in_sizes, int n_in,
                              void* d_out, int out_size) {
    const int*   z      = (const int*)  d_in[0];
    const float* pos    = (const float*)d_in[1];
    const int*   batch  = (const int*)  d_in[2];
    const int*   ei     = (const int*)  d_in[3];
    const float* emb    = (const float*)d_in[4];
    const float* mlp_w1 = (const float*)d_in[5];
    const float* mlp_b1 = (const float*)d_in[6];
    const float* mlp_w2 = (const float*)d_in[7];
    const float* mlp_b2 = (const float*)d_in[8];
    const float* cf1_w  = (const float*)d_in[9];
    const float* cf2_w  = (const float*)d_in[10];
    const float* cf2_b  = (const float*)d_in[11];
    const float* lin_w  = (const float*)d_in[12];
    const float* lin_b  = (const float*)d_in[13];
    const float* out1_w = (const float*)d_in[14];
    const float* out1_b = (const float*)d_in[15];
    const float* out2_w = (const float*)d_in[16];
    const float* out2_b = (const float*)d_in[17];
    float* out = (float*)d_out;

    // single memset zeroes hist counts + graph accumulator
    void* zp = nullptr;
    cudaGetSymbolAddress(&zp, g_base);
    cudaMemsetAsync(zp, 0, ZBASE_INTS * sizeof(int));

    // independent work first
    k_table    <<<NB * (MTAB / 32), 64>>>(mlp_w1, mlp_b1, mlp_w2, mlp_b2);
    k_embed_cf1<<<GEMM_GRID, 256>>>(z, emb, cf1_w);
    k_hist     <<<(NEDGE / 4 + 255) / 256, 256>>>(pos, ei);
    k_scan1    <<<NSCANB, 1024>>>();
    k_scan2    <<<1, 64>>>();
    k_scan3    <<<NSCANB, 1024>>>();
    k_scatter  <<<(NEDGE / 4 + 255) / 256, 256>>>(ei);

    for (int t = 0; t < NB; t++) {
        k_agg<<<(NATOMS + 7) / 8, 256>>>(t);
        const float* w1 = cf2_w + (size_t)t * 64 * 64;
        const float* b1 = cf2_b + (size_t)t * 64;
        const float* w2 = lin_w + (size_t)t * 64 * 64;
        const float* b2 = lin_b + (size_t)t * 64;
        if (t + 1 < NB)
            k_cf2lin<true><<<GEMM_GRID, 256>>>(w1, b1, w2, b2,
                cf1_w + (size_t)(t + 1) * 64 * 64, batch);
        else
            k_cf2lin<false><<<GEMM_GRID, 256>>>(w1, b1, w2, b2, nullptr, batch);
    }

    k_head<<<1, 256>>>(out1_w, out1_b, out2_w, out2_b, out);
}